// round 13
// baseline (speedup 1.0000x reference)
#include <cuda_runtime.h>
#include <cuda_bf16.h>
#include <cstdint>

// Problem constants
#define NN 4096
#define BB 16
#define CC 256
#define HH 128
#define C2 512
#define NTOK (NN*BB)       // 65536
#define MAXSEL 2048
#define BAND 3e-3f
#define RCCAP 16384
#define PAIRBLKS (4*32*16)         // 2048
#define COPYBLKS (NTOK*(CC/4)/256) // 16384

// -------------------- device scratch --------------------
__device__ float g_sig[NTOK];
__device__ unsigned char g_valid[NTOK];
__device__ unsigned char g_selflag[NTOK];
__device__ int g_mask_kind;
__device__ int g_split_idx[BB*MAXSEL];
__device__ int g_discard_idx[BB*MAXSEL];
__device__ int g_mc[BB];
__device__ __nv_bfloat16 g_ws_hi[CC*C2];
__device__ __nv_bfloat16 g_ws_lo[CC*C2];
__device__ __nv_bfloat16 g_w1s[2][CC*HH];     // 2-way split of w1
__device__ int g_cnt0, g_cnt1;
__device__ int g_list0[RCCAP], g_list1[RCCAP];
__device__ unsigned g_thr[2][BB];             // [set][b] phase-A threshold bits

// -------------------- mask dtype detection --------------------
__global__ void detect_mask_kernel(const unsigned char* __restrict__ m) {
    __shared__ int f3, foff;
    if (threadIdx.x == 0) { f3 = 0; foff = 0; }
    __syncthreads();
    int l3 = 0, loff = 0;
    for (int i = threadIdx.x; i < NTOK; i += 1024) {
        unsigned char v = m[i];
        if (v == 0x3f) l3 = 1;
        if (v && (i & 3)) loff = 1;
    }
    if (l3) f3 = 1;
    if (loff) foff = 1;
    __syncthreads();
    if (threadIdx.x == 0) g_mask_kind = f3 ? 2 : (foff ? 0 : 1);
}

__global__ void expand_mask_kernel(const void* __restrict__ m) {
    int i = blockIdx.x * 256 + threadIdx.x;
    if (i >= NTOK) return;
    if (i == 0) { g_cnt0 = 0; g_cnt1 = 0; }
    int kind = g_mask_kind;
    int v;
    if (kind == 0)      v = ((const unsigned char*)m)[i];
    else if (kind == 1) v = ((const int*)m)[i];
    else                v = (((const float*)m)[i] != 0.0f);
    g_valid[i] = (v == 0) ? 1 : 0;
    g_selflag[i] = 0;
}

// -------------------- combined weight pre-split (ws 2-way, w1 2-way) --------------------
__global__ void prep_weights_kernel(const float* __restrict__ ws, const float* __restrict__ w1) {
    int i = blockIdx.x * 256 + threadIdx.x;
    if (i < CC * C2) {
        float w = ws[i];
        __nv_bfloat16 h = __float2bfloat16(w);
        g_ws_hi[i] = h;
        g_ws_lo[i] = __float2bfloat16(w - __bfloat162float(h));
    }
    if (i < CC * HH) {
        float w = w1[i];
        __nv_bfloat16 a0 = __float2bfloat16(w);
        __nv_bfloat16 a1 = __float2bfloat16(w - __bfloat162float(a0));
        g_w1s[0][i] = a0; g_w1s[1][i] = a1;
    }
}

// -------------------- mma helpers --------------------
__device__ __forceinline__ uint32_t smem_u32(const void* p) {
    return (uint32_t)__cvta_generic_to_shared(p);
}
__device__ __forceinline__ void ldsm_x4(uint32_t& r0, uint32_t& r1, uint32_t& r2, uint32_t& r3, uint32_t addr) {
    asm volatile("ldmatrix.sync.aligned.m8n8.x4.shared.b16 {%0,%1,%2,%3}, [%4];"
                 : "=r"(r0), "=r"(r1), "=r"(r2), "=r"(r3) : "r"(addr));
}
__device__ __forceinline__ void ldsm_x4t(uint32_t& r0, uint32_t& r1, uint32_t& r2, uint32_t& r3, uint32_t addr) {
    asm volatile("ldmatrix.sync.aligned.m8n8.x4.trans.shared.b16 {%0,%1,%2,%3}, [%4];"
                 : "=r"(r0), "=r"(r1), "=r"(r2), "=r"(r3) : "r"(addr));
}
__device__ __forceinline__ void mma_bf16(float* d, const uint32_t* a, const uint32_t* bfr) {
    asm volatile("mma.sync.aligned.m16n8k16.row.col.f32.bf16.bf16.f32 "
                 "{%0,%1,%2,%3},{%4,%5,%6,%7},{%8,%9},{%0,%1,%2,%3};"
                 : "+f"(d[0]), "+f"(d[1]), "+f"(d[2]), "+f"(d[3])
                 : "r"(a[0]), "r"(a[1]), "r"(a[2]), "r"(a[3]), "r"(bfr[0]), "r"(bfr[1]));
}

// -------------------- gating pass-1 (bf16x2 split, 3 products, double-buffered smem) -----
__global__ void __launch_bounds__(256) gating_mma_kernel(
    const float* __restrict__ x, const float* __restrict__ b1v,
    const float* __restrict__ w2v, const float* __restrict__ b2v)
{
    __shared__ __nv_bfloat16 sA[2][2][128][24];   // [buf][comp][row][col]
    __shared__ __nv_bfloat16 sB[2][2][16][136];
    __shared__ float b1s[HH], w2s[HH];
    __shared__ float red[128][5];

    int tid = threadIdx.x;
    int lane = tid & 31;
    int wid = tid >> 5;
    int wm = wid >> 2, wn = wid & 3;
    int tM = blockIdx.x * 128;

    if (tid < HH) { b1s[tid] = b1v[tid]; w2s[tid] = w2v[tid]; }

    float acc[4][4][4];
    #pragma unroll
    for (int m = 0; m < 4; m++)
        #pragma unroll
        for (int n = 0; n < 4; n++)
            #pragma unroll
            for (int q = 0; q < 4; q++) acc[m][n][q] = 0.f;

    int ar = tid >> 1, aseg = (tid & 1) * 8;
    const float* xrow = &x[(tM + ar) * CC + aseg];
    int br = tid >> 4, bc = (tid & 15) * 8;

    float4 f0, f1;
    uint4 bR0, bR1;

#define GFETCH(kt) { \
    f0 = *(const float4*)&xrow[kt]; \
    f1 = *(const float4*)&xrow[(kt) + 4]; \
    bR0 = *(const uint4*)&g_w1s[0][((kt) + br) * HH + bc]; \
    bR1 = *(const uint4*)&g_w1s[1][((kt) + br) * HH + bc]; }

#define GSTORE(db) { \
    float fv[8] = {f0.x, f0.y, f0.z, f0.w, f1.x, f1.y, f1.z, f1.w}; \
    __nv_bfloat162 p0[4], p1[4]; \
    _Pragma("unroll") \
    for (int q = 0; q < 4; q++) { \
        float va = fv[2*q], vb = fv[2*q+1]; \
        __nv_bfloat16 a0 = __float2bfloat16(va), b0 = __float2bfloat16(vb); \
        __nv_bfloat16 a1 = __float2bfloat16(va - __bfloat162float(a0)); \
        __nv_bfloat16 b1h = __float2bfloat16(vb - __bfloat162float(b0)); \
        p0[q] = __nv_bfloat162(a0, b0); \
        p1[q] = __nv_bfloat162(a1, b1h); \
    } \
    *(uint4*)&sA[db][0][ar][aseg] = *(uint4*)p0; \
    *(uint4*)&sA[db][1][ar][aseg] = *(uint4*)p1; \
    *(uint4*)&sB[db][0][br][bc] = bR0; \
    *(uint4*)&sB[db][1][br][bc] = bR1; }

#define GCOMPUTE(db) { \
    uint32_t aF[2][4][4]; \
    _Pragma("unroll") \
    for (int c = 0; c < 2; c++) \
        _Pragma("unroll") \
        for (int m = 0; m < 4; m++) { \
            int arow = wm * 64 + m * 16 + (lane & 15); \
            int acol = (lane >> 4) * 8; \
            ldsm_x4(aF[c][m][0], aF[c][m][1], aF[c][m][2], aF[c][m][3], \
                    smem_u32(&sA[db][c][arow][acol])); \
        } \
    _Pragma("unroll") \
    for (int cj = 0; cj < 2; cj++) { \
        uint32_t bFj[4][2]; \
        _Pragma("unroll") \
        for (int g = 0; g < 2; g++) { \
            int brow = lane & 15; \
            int bcl = wn * 32 + g * 16 + (lane >> 4) * 8; \
            uint32_t r0, r1, r2, r3; \
            ldsm_x4t(r0, r1, r2, r3, smem_u32(&sB[db][cj][brow][bcl])); \
            bFj[2*g][0] = r0; bFj[2*g][1] = r1; \
            bFj[2*g+1][0] = r2; bFj[2*g+1][1] = r3; \
        } \
        _Pragma("unroll") \
        for (int ci = 0; ci < 2; ci++) { \
            if (ci + cj > 1) continue; \
            _Pragma("unroll") \
            for (int m = 0; m < 4; m++) \
                _Pragma("unroll") \
                for (int n = 0; n < 4; n++) \
                    mma_bf16(acc[m][n], aF[ci][m], bFj[n]); \
        } \
    } }

    GFETCH(0); GSTORE(0); __syncthreads();
    int db = 0;
    for (int kt = 16; kt < CC; kt += 16) {
        GFETCH(kt);
        GCOMPUTE(db);
        GSTORE(db ^ 1);
        __syncthreads();
        db ^= 1;
    }
    GCOMPUTE(db);

#undef GFETCH
#undef GSTORE
#undef GCOMPUTE

    #pragma unroll
    for (int m = 0; m < 4; m++) {
        #pragma unroll
        for (int hr = 0; hr < 2; hr++) {
            float p = 0.f;
            #pragma unroll
            for (int n = 0; n < 4; n++) {
                int c = wn * 32 + n * 8 + (lane & 3) * 2;
                float h0 = fmaxf(acc[m][n][hr*2]   + b1s[c],   0.f);
                float h1 = fmaxf(acc[m][n][hr*2+1] + b1s[c+1], 0.f);
                p = fmaf(h0, w2s[c], p);
                p = fmaf(h1, w2s[c+1], p);
            }
            p += __shfl_xor_sync(~0u, p, 1);
            p += __shfl_xor_sync(~0u, p, 2);
            if ((lane & 3) == 0) red[wm*64 + m*16 + (lane>>2) + hr*8][wn] = p;
        }
    }
    __syncthreads();
    if (tid < 128) {
        float lg = b2v[0] + red[tid][0] + red[tid][1] + red[tid][2] + red[tid][3];
        float s;
        if (lg >= 0.f) { s = 1.f / (1.f + expf(-lg)); }
        else           { float e = expf(lg); s = e / (1.f + e); }
        int t = tM + tid;
        int idx = (t & (BB-1)) * NN + (t >> 4);
        g_sig[idx] = s;
        if (g_valid[idx] && fabsf(s - 0.5f) <= BAND) {
            int p = atomicAdd(&g_cnt0, 1);
            if (p < RCCAP) g_list0[p] = idx;
        }
    }
}

// -------------------- exact fp32 recompute of flagged tokens --------------------
__global__ void __launch_bounds__(128) recheck_kernel(
    const float* __restrict__ x, const float* __restrict__ w1,
    const float* __restrict__ b1v, const float* __restrict__ w2v,
    const float* __restrict__ b2v, int which)
{
    __shared__ float wred[4];
    int cnt = min(which ? g_cnt1 : g_cnt0, RCCAP);
    const int* list = which ? g_list1 : g_list0;
    int j = threadIdx.x;
    for (int it = blockIdx.x; it < cnt; it += gridDim.x) {
        int tok = list[it];
        int b = tok >> 12, n = tok & (NN - 1);
        const float* xr = &x[(n * BB + b) * CC];
        float a = 0.f;
        #pragma unroll 8
        for (int k = 0; k < CC; k++) a = fmaf(xr[k], w1[k * HH + j], a);
        float h = fmaxf(a + b1v[j], 0.f);
        float p = h * w2v[j];
        #pragma unroll
        for (int o = 16; o; o >>= 1) p += __shfl_down_sync(~0u, p, o);
        if ((j & 31) == 0) wred[j >> 5] = p;
        __syncthreads();
        if (j == 0) {
            float lg = b2v[0] + wred[0] + wred[1] + wred[2] + wred[3];
            float s;
            if (lg >= 0.f) { s = 1.f / (1.f + expf(-lg)); }
            else           { float e = expf(lg); s = e / (1.f + e); }
            g_sig[tok] = s;
        }
        __syncthreads();
    }
}

// -------------------- block scan (inclusive) via warp shuffles --------------------
__device__ __forceinline__ int block_scan_incl(int v, int tid, int* warpsum) {
    __syncthreads();
    int lane = tid & 31, w = tid >> 5;
    int s = v;
    #pragma unroll
    for (int o = 1; o < 32; o <<= 1) {
        int t = __shfl_up_sync(~0u, s, o);
        if (lane >= o) s += t;
    }
    if (lane == 31) warpsum[w] = s;
    __syncthreads();
    if (w == 0) {
        int ws = (lane < 16) ? warpsum[lane] : 0;
        #pragma unroll
        for (int o = 1; o < 16; o <<= 1) {
            int t = __shfl_up_sync(~0u, ws, o);
            if (lane >= o) ws += t;
        }
        if (lane < 16) warpsum[lane] = ws;
    }
    __syncthreads();
    return s + ((w > 0) ? warpsum[w - 1] : 0);
}

// -------------------- selection: 3-pass radix select; phase 0 = threshold + band flags ----
__global__ void __launch_bounds__(512) select_kernel(int phase) {
    const int T = 512;
    int set = blockIdx.x;
    int b = blockIdx.y;
    int tid = threadIdx.x;

    __shared__ int hist[4096];
    __shared__ int sh[T];
    __shared__ int s_warp[16];
    __shared__ int s_scal[8];

    const float* sig = g_sig + b * NN;
    const unsigned char* vd = g_valid + b * NN;

    if (tid < 8) s_scal[tid] = 0;
    __syncthreads();
    int cs = 0, cd = 0;
    for (int n = tid; n < NN; n += T) {
        if (vd[n]) { if (sig[n] >= 0.5f) cs++; else cd++; }
    }
    #pragma unroll
    for (int o = 16; o; o >>= 1) {
        cs += __shfl_down_sync(~0u, cs, o);
        cd += __shfl_down_sync(~0u, cd, o);
    }
    if ((tid & 31) == 0) { atomicAdd(&s_scal[0], cs); atomicAdd(&s_scal[1], cd); }
    __syncthreads();
    int mc = min(s_scal[0], s_scal[1]);
    if (phase == 1 && set == 0 && tid == 0) g_mc[b] = mc;
    if (mc == 0) {
        if (phase == 0 && tid == 0) g_thr[set][b] = 0x7FC00000u;
        return;
    }

    int k = mc;
    unsigned thrV = 0, hm = 0;
    const int widths[3] = {12, 10, 10};
    const int shifts[3] = {20, 10, 0};

    for (int p = 0; p < 3; p++) {
        int shift = shifts[p];
        int nb2 = 1 << widths[p];
        int CHn = nb2 >> 9;
        for (int i = tid; i < nb2; i += T) hist[i] = 0;
        __syncthreads();
        for (int n = tid; n < NN; n += T) {
            if (!vd[n]) continue;
            float s = sig[n];
            bool in = set ? (s < 0.5f) : (s >= 0.5f);
            if (!in) continue;
            unsigned bits = __float_as_uint(s);
            if ((bits & hm) != thrV) continue;
            atomicAdd(&hist[(bits >> shift) & (nb2 - 1)], 1);
        }
        __syncthreads();
        int base = tid * CHn, csum = 0;
        for (int i = 0; i < CHn; i++) csum += hist[base + i];
        int P = block_scan_incl(csum, tid, s_warp);
        sh[tid] = P;
        if (tid == T - 1) s_scal[5] = P;
        __syncthreads();
        int Tt = s_scal[5];
        if (P - csum <= Tt - k && P > Tt - k) s_scal[2] = tid;
        __syncthreads();
        if (tid == 0) {
            int cc = s_scal[2];
            int above = Tt - sh[cc];
            int dg = cc * CHn;
            for (int d = cc * CHn + CHn - 1; d >= cc * CHn; d--) {
                int c = hist[d];
                if (above + c >= k) { dg = d; break; }
                above += c;
            }
            s_scal[3] = dg;
            s_scal[4] = k - above;
        }
        __syncthreads();
        thrV |= ((unsigned)s_scal[3]) << shift;
        k = s_scal[4];
        hm |= ((unsigned)(nb2 - 1)) << shift;
        __syncthreads();
    }

    if (phase == 0) {
        if (tid == 0) g_thr[set][b] = thrV;
        // fused flagthr: this block owns (set, b); flag in-set tokens near threshold
        float tf = __uint_as_float(thrV);
        for (int n = tid; n < NN; n += T) {
            if (!vd[n]) continue;
            float s = sig[n];
            bool in = set ? (s < 0.5f) : (s >= 0.5f);
            if (in && fabsf(s - tf) <= BAND) {
                int p = atomicAdd(&g_cnt1, 1);
                if (p < RCCAP) g_list1[p] = b * NN + n;
            }
        }
        return;
    }
    int k_rem = k;

    int n0 = tid * 8;
    unsigned char gtf[8], eqf[8];
    int lgt = 0, leq = 0;
    #pragma unroll
    for (int q = 0; q < 8; q++) {
        int n = n0 + q;
        float s = sig[n];
        bool in = vd[n] && (set ? (s < 0.5f) : (s >= 0.5f));
        unsigned bits = __float_as_uint(s);
        gtf[q] = (in && bits > thrV) ? 1 : 0;
        eqf[q] = (in && bits == thrV) ? 1 : 0;
        lgt += gtf[q]; leq += eqf[q];
    }
    int own = lgt | (leq << 16);
    int pref = block_scan_incl(own, tid, s_warp) - own;
    int pgt = pref & 0xFFFF, peq = pref >> 16;
    int* dst = set ? g_discard_idx : g_split_idx;
    unsigned char* flag = g_selflag + b * NN;
    int cgi = 0, cei = 0;
    #pragma unroll
    for (int q = 0; q < 8; q++) {
        int n = n0 + q;
        if (gtf[q]) {
            int pos = (pgt + cgi) + min(peq + cei, k_rem);
            dst[b * MAXSEL + pos] = n;
            flag[n] = 1;
            cgi++;
        } else if (eqf[q]) {
            int er = peq + cei;
            if (er < k_rem) {
                int pos = (pgt + cgi) + er;
                dst[b * MAXSEL + pos] = n;
                flag[n] = 1;
            }
            cei++;
        }
    }
}

// -------------------- merged tail: pair GEMM blocks + flag-gated copy blocks ------------
__global__ void __launch_bounds__(256) tail_kernel(
    const float* __restrict__ x, const float* __restrict__ bsv, float* __restrict__ out)
{
    int tid = threadIdx.x;

    if (blockIdx.x >= PAIRBLKS) {
        // ---- copy branch ----
        int idx = (blockIdx.x - PAIRBLKS) * 256 + tid;   // NTOK*64 float4 total
        int t = idx >> 6;
        int b = t & (BB - 1), n = t >> 4;
        if (!g_selflag[b * NN + n])
            ((float4*)out)[idx] = ((const float4*)x)[idx];
        return;
    }

    // ---- pair branch: decode (nb0, i0, b) from linear block id ----
    int j = blockIdx.x;
    int nbq = j & 3;            // 0..3
    int yq  = (j >> 2) & 31;    // 0..31
    int b   = j >> 7;           // 0..15
    int mc = g_mc[b];
    int i0 = yq * 64;
    if (i0 >= mc) return;
    int nb0 = nbq * 128;
    int half = nb0 >> 8;

    __shared__ __nv_bfloat16 sAhi[2][64][24], sAlo[2][64][24];
    __shared__ __nv_bfloat16 sBhi[2][16][136], sBlo[2][16][136];
    __shared__ float bss[128];
    __shared__ int srcI[64], tgtI[64];

    int lane = tid & 31;
    int wid = tid >> 5;

    if (tid < 128) bss[tid] = bsv[nb0 + tid];
    if (tid < 64) {
        int i = i0 + tid;
        if (i < mc) {
            int m = g_split_idx[b * MAXSEL + i];
            srcI[tid] = m;
            tgtI[tid] = half ? g_discard_idx[b * MAXSEL + i] : m;
        } else { srcI[tid] = 0; tgtI[tid] = -1; }
    }
    __syncthreads();

    int m_off = (wid >> 2) * 32;
    int n_off = (wid & 3) * 32;

    float acc[2][4][4];
    #pragma unroll
    for (int m = 0; m < 2; m++)
        #pragma unroll
        for (int jj = 0; jj < 4; jj++)
            #pragma unroll
            for (int q = 0; q < 4; q++) acc[m][jj][q] = 0.f;

    int ar = tid >> 2, aseg = (tid & 3) * 4;
    const float* xrow = &x[(srcI[ar] * BB + b) * CC + aseg];
    int br = tid >> 4, bcol = (tid & 15) * 8;

    float4 f0;
    uint4 bhR, blR;

#define PFETCH(kt) { \
    f0 = *(const float4*)&xrow[kt]; \
    bhR = *(const uint4*)&g_ws_hi[((kt) + br) * C2 + nb0 + bcol]; \
    blR = *(const uint4*)&g_ws_lo[((kt) + br) * C2 + nb0 + bcol]; }

#define PSTORE(db) { \
    float fv[4] = {f0.x, f0.y, f0.z, f0.w}; \
    __nv_bfloat162 hp[2], lp[2]; \
    _Pragma("unroll") \
    for (int q = 0; q < 2; q++) { \
        __nv_bfloat16 h0 = __float2bfloat16(fv[2*q]); \
        __nv_bfloat16 h1 = __float2bfloat16(fv[2*q+1]); \
        __nv_bfloat16 l0 = __float2bfloat16(fv[2*q]   - __bfloat162float(h0)); \
        __nv_bfloat16 l1 = __float2bfloat16(fv[2*q+1] - __bfloat162float(h1)); \
        hp[q] = __nv_bfloat162(h0, h1); \
        lp[q] = __nv_bfloat162(l0, l1); \
    } \
    *(uint2*)&sAhi[db][ar][aseg] = *(uint2*)hp; \
    *(uint2*)&sAlo[db][ar][aseg] = *(uint2*)lp; \
    *(uint4*)&sBhi[db][br][bcol] = bhR; \
    *(uint4*)&sBlo[db][br][bcol] = blR; }

#define PCOMPUTE(db) { \
    uint32_t ahi[2][4], alo[2][4], bhi[4][2], blo[4][2]; \
    _Pragma("unroll") \
    for (int m = 0; m < 2; m++) { \
        int arow = m_off + m * 16 + (lane & 15); \
        int acol = (lane >> 4) * 8; \
        ldsm_x4(ahi[m][0], ahi[m][1], ahi[m][2], ahi[m][3], smem_u32(&sAhi[db][arow][acol])); \
        ldsm_x4(alo[m][0], alo[m][1], alo[m][2], alo[m][3], smem_u32(&sAlo[db][arow][acol])); \
    } \
    _Pragma("unroll") \
    for (int g = 0; g < 2; g++) { \
        int brow = lane & 15; \
        int bcl = n_off + g * 16 + (lane >> 4) * 8; \
        uint32_t r0, r1, r2, r3; \
        ldsm_x4t(r0, r1, r2, r3, smem_u32(&sBhi[db][brow][bcl])); \
        bhi[2*g][0] = r0; bhi[2*g][1] = r1; bhi[2*g+1][0] = r2; bhi[2*g+1][1] = r3; \
        ldsm_x4t(r0, r1, r2, r3, smem_u32(&sBlo[db][brow][bcl])); \
        blo[2*g][0] = r0; blo[2*g][1] = r1; blo[2*g+1][0] = r2; blo[2*g+1][1] = r3; \
    } \
    _Pragma("unroll") \
    for (int m = 0; m < 2; m++) \
        _Pragma("unroll") \
        for (int jj = 0; jj < 4; jj++) { \
            mma_bf16(acc[m][jj], ahi[m], bhi[jj]); \
            mma_bf16(acc[m][jj], ahi[m], blo[jj]); \
            mma_bf16(acc[m][jj], alo[m], bhi[jj]); \
        } }

    PFETCH(0); PSTORE(0); __syncthreads();
    int db = 0;
    for (int kt = 16; kt < CC; kt += 16) {
        PFETCH(kt);
        PCOMPUTE(db);
        PSTORE(db ^ 1);
        __syncthreads();
        db ^= 1;
    }
    PCOMPUTE(db);

#undef PFETCH
#undef PSTORE
#undef PCOMPUTE

    #pragma unroll
    for (int m = 0; m < 2; m++) {
        #pragma unroll
        for (int hr = 0; hr < 2; hr++) {
            int r = m_off + m * 16 + (lane >> 2) + hr * 8;
            int tg = tgtI[r];
            if (tg < 0) continue;
            float* orow = &out[(tg * BB + b) * CC];
            #pragma unroll
            for (int jj = 0; jj < 4; jj++) {
                int cl = n_off + jj * 8 + (lane & 3) * 2;
                int cg = (nb0 + cl) & (CC - 1);
                float v0 = fmaxf(acc[m][jj][hr*2]     + bss[cl],     0.f);
                float v1 = fmaxf(acc[m][jj][hr*2 + 1] + bss[cl + 1], 0.f);
                float2 v = make_float2(v0, v1);
                *(float2*)&orow[cg] = v;
            }
        }
    }
}

// -------------------- launch --------------------
extern "C" void kernel_launch(void* const* d_in, const int* in_sizes, int n_in,
                              void* d_out, int out_size) {
    const float* x   = (const float*)d_in[0];
    const void*  msk = d_in[1];
    const float* w1  = (const float*)d_in[2];
    const float* b1  = (const float*)d_in[3];
    const float* w2  = (const float*)d_in[4];
    const float* b2  = (const float*)d_in[5];
    const float* ws  = (const float*)d_in[6];
    const float* bs  = (const float*)d_in[7];
    float* out = (float*)d_out;

    detect_mask_kernel<<<1, 1024>>>((const unsigned char*)msk);
    expand_mask_kernel<<<NTOK / 256, 256>>>(msk);
    prep_weights_kernel<<<(CC * C2) / 256, 256>>>(ws, w1);

    gating_mma_kernel<<<NTOK / 128, 256>>>(x, b1, w2, b2);
    recheck_kernel<<<512, 128>>>(x, w1, b1, w2, b2, 0);
    select_kernel<<<dim3(2, BB), 512>>>(0);
    recheck_kernel<<<512, 128>>>(x, w1, b1, w2, b2, 1);
    select_kernel<<<dim3(2, BB), 512>>>(1);
    tail_kernel<<<PAIRBLKS + COPYBLKS, 256>>>(x, bs, out);
}

// round 16
// speedup vs baseline: 1.0421x; 1.0421x over previous
#include <cuda_runtime.h>
#include <cuda_bf16.h>
#include <cstdint>

// Problem constants
#define NN 4096
#define BB 16
#define CC 256
#define HH 128
#define C2 512
#define NTOK (NN*BB)       // 65536
#define MAXSEL 2048
#define BAND 3e-3f
#define RCCAP 16384

// -------------------- device scratch --------------------
__device__ float g_sig[NTOK];
__device__ unsigned char g_valid[NTOK];
__device__ unsigned char g_selflag[NTOK];
__device__ int g_mask_kind;
__device__ int g_split_idx[BB*MAXSEL];
__device__ int g_discard_idx[BB*MAXSEL];
__device__ int g_mc[BB];
__device__ __nv_bfloat16 g_ws_hi[CC*C2];
__device__ __nv_bfloat16 g_ws_lo[CC*C2];
__device__ __nv_bfloat16 g_w1s[2][CC*HH];     // 2-way split of w1
__device__ int g_cnt0, g_cnt1;
__device__ int g_list0[RCCAP], g_list1[RCCAP];
__device__ unsigned g_thr[2][BB];             // [set][b] phase-A threshold bits

// -------------------- mask dtype detection --------------------
__global__ void detect_mask_kernel(const unsigned char* __restrict__ m) {
    __shared__ int f3, foff;
    if (threadIdx.x == 0) { f3 = 0; foff = 0; }
    __syncthreads();
    int l3 = 0, loff = 0;
    for (int i = threadIdx.x; i < NTOK; i += 1024) {
        unsigned char v = m[i];
        if (v == 0x3f) l3 = 1;
        if (v && (i & 3)) loff = 1;
    }
    if (l3) f3 = 1;
    if (loff) foff = 1;
    __syncthreads();
    if (threadIdx.x == 0) g_mask_kind = f3 ? 2 : (foff ? 0 : 1);
}

__global__ void expand_mask_kernel(const void* __restrict__ m) {
    int i = blockIdx.x * 256 + threadIdx.x;
    if (i >= NTOK) return;
    if (i == 0) { g_cnt0 = 0; g_cnt1 = 0; }
    int kind = g_mask_kind;
    int v;
    if (kind == 0)      v = ((const unsigned char*)m)[i];
    else if (kind == 1) v = ((const int*)m)[i];
    else                v = (((const float*)m)[i] != 0.0f);
    g_valid[i] = (v == 0) ? 1 : 0;
    g_selflag[i] = 0;
}

// -------------------- combined weight pre-split (ws 2-way, w1 2-way) --------------------
__global__ void prep_weights_kernel(const float* __restrict__ ws, const float* __restrict__ w1) {
    int i = blockIdx.x * 256 + threadIdx.x;
    if (i < CC * C2) {
        float w = ws[i];
        __nv_bfloat16 h = __float2bfloat16(w);
        g_ws_hi[i] = h;
        g_ws_lo[i] = __float2bfloat16(w - __bfloat162float(h));
    }
    if (i < CC * HH) {
        float w = w1[i];
        __nv_bfloat16 a0 = __float2bfloat16(w);
        __nv_bfloat16 a1 = __float2bfloat16(w - __bfloat162float(a0));
        g_w1s[0][i] = a0; g_w1s[1][i] = a1;
    }
}

// -------------------- mma helpers --------------------
__device__ __forceinline__ uint32_t smem_u32(const void* p) {
    return (uint32_t)__cvta_generic_to_shared(p);
}
__device__ __forceinline__ void ldsm_x4(uint32_t& r0, uint32_t& r1, uint32_t& r2, uint32_t& r3, uint32_t addr) {
    asm volatile("ldmatrix.sync.aligned.m8n8.x4.shared.b16 {%0,%1,%2,%3}, [%4];"
                 : "=r"(r0), "=r"(r1), "=r"(r2), "=r"(r3) : "r"(addr));
}
__device__ __forceinline__ void ldsm_x4t(uint32_t& r0, uint32_t& r1, uint32_t& r2, uint32_t& r3, uint32_t addr) {
    asm volatile("ldmatrix.sync.aligned.m8n8.x4.trans.shared.b16 {%0,%1,%2,%3}, [%4];"
                 : "=r"(r0), "=r"(r1), "=r"(r2), "=r"(r3) : "r"(addr));
}
__device__ __forceinline__ void mma_bf16(float* d, const uint32_t* a, const uint32_t* bfr) {
    asm volatile("mma.sync.aligned.m16n8k16.row.col.f32.bf16.bf16.f32 "
                 "{%0,%1,%2,%3},{%4,%5,%6,%7},{%8,%9},{%0,%1,%2,%3};"
                 : "+f"(d[0]), "+f"(d[1]), "+f"(d[2]), "+f"(d[3])
                 : "r"(a[0]), "r"(a[1]), "r"(a[2]), "r"(a[3]), "r"(bfr[0]), "r"(bfr[1]));
}

// -------------------- gating pass-1 (bf16x2 split, 3 products, double-buffered smem) -----
__global__ void __launch_bounds__(256) gating_mma_kernel(
    const float* __restrict__ x, const float* __restrict__ b1v,
    const float* __restrict__ w2v, const float* __restrict__ b2v)
{
    __shared__ __nv_bfloat16 sA[2][2][128][24];   // [buf][comp][row][col]
    __shared__ __nv_bfloat16 sB[2][2][16][136];
    __shared__ float b1s[HH], w2s[HH];
    __shared__ float red[128][5];

    int tid = threadIdx.x;
    int lane = tid & 31;
    int wid = tid >> 5;
    int wm = wid >> 2, wn = wid & 3;
    int tM = blockIdx.x * 128;

    if (tid < HH) { b1s[tid] = b1v[tid]; w2s[tid] = w2v[tid]; }

    float acc[4][4][4];
    #pragma unroll
    for (int m = 0; m < 4; m++)
        #pragma unroll
        for (int n = 0; n < 4; n++)
            #pragma unroll
            for (int q = 0; q < 4; q++) acc[m][n][q] = 0.f;

    int ar = tid >> 1, aseg = (tid & 1) * 8;
    const float* xrow = &x[(tM + ar) * CC + aseg];
    int br = tid >> 4, bc = (tid & 15) * 8;

    float4 f0, f1;
    uint4 bR0, bR1;

#define GFETCH(kt) { \
    f0 = *(const float4*)&xrow[kt]; \
    f1 = *(const float4*)&xrow[(kt) + 4]; \
    bR0 = *(const uint4*)&g_w1s[0][((kt) + br) * HH + bc]; \
    bR1 = *(const uint4*)&g_w1s[1][((kt) + br) * HH + bc]; }

#define GSTORE(db) { \
    float fv[8] = {f0.x, f0.y, f0.z, f0.w, f1.x, f1.y, f1.z, f1.w}; \
    __nv_bfloat162 p0[4], p1[4]; \
    _Pragma("unroll") \
    for (int q = 0; q < 4; q++) { \
        float va = fv[2*q], vb = fv[2*q+1]; \
        __nv_bfloat16 a0 = __float2bfloat16(va), b0 = __float2bfloat16(vb); \
        __nv_bfloat16 a1 = __float2bfloat16(va - __bfloat162float(a0)); \
        __nv_bfloat16 b1h = __float2bfloat16(vb - __bfloat162float(b0)); \
        p0[q] = __nv_bfloat162(a0, b0); \
        p1[q] = __nv_bfloat162(a1, b1h); \
    } \
    *(uint4*)&sA[db][0][ar][aseg] = *(uint4*)p0; \
    *(uint4*)&sA[db][1][ar][aseg] = *(uint4*)p1; \
    *(uint4*)&sB[db][0][br][bc] = bR0; \
    *(uint4*)&sB[db][1][br][bc] = bR1; }

#define GCOMPUTE(db) { \
    uint32_t aF[2][4][4]; \
    _Pragma("unroll") \
    for (int c = 0; c < 2; c++) \
        _Pragma("unroll") \
        for (int m = 0; m < 4; m++) { \
            int arow = wm * 64 + m * 16 + (lane & 15); \
            int acol = (lane >> 4) * 8; \
            ldsm_x4(aF[c][m][0], aF[c][m][1], aF[c][m][2], aF[c][m][3], \
                    smem_u32(&sA[db][c][arow][acol])); \
        } \
    _Pragma("unroll") \
    for (int cj = 0; cj < 2; cj++) { \
        uint32_t bFj[4][2]; \
        _Pragma("unroll") \
        for (int g = 0; g < 2; g++) { \
            int brow = lane & 15; \
            int bcl = wn * 32 + g * 16 + (lane >> 4) * 8; \
            uint32_t r0, r1, r2, r3; \
            ldsm_x4t(r0, r1, r2, r3, smem_u32(&sB[db][cj][brow][bcl])); \
            bFj[2*g][0] = r0; bFj[2*g][1] = r1; \
            bFj[2*g+1][0] = r2; bFj[2*g+1][1] = r3; \
        } \
        _Pragma("unroll") \
        for (int ci = 0; ci < 2; ci++) { \
            if (ci + cj > 1) continue; \
            _Pragma("unroll") \
            for (int m = 0; m < 4; m++) \
                _Pragma("unroll") \
                for (int n = 0; n < 4; n++) \
                    mma_bf16(acc[m][n], aF[ci][m], bFj[n]); \
        } \
    } }

    GFETCH(0); GSTORE(0); __syncthreads();
    int db = 0;
    for (int kt = 16; kt < CC; kt += 16) {
        GFETCH(kt);
        GCOMPUTE(db);
        GSTORE(db ^ 1);
        __syncthreads();
        db ^= 1;
    }
    GCOMPUTE(db);

#undef GFETCH
#undef GSTORE
#undef GCOMPUTE

    #pragma unroll
    for (int m = 0; m < 4; m++) {
        #pragma unroll
        for (int hr = 0; hr < 2; hr++) {
            float p = 0.f;
            #pragma unroll
            for (int n = 0; n < 4; n++) {
                int c = wn * 32 + n * 8 + (lane & 3) * 2;
                float h0 = fmaxf(acc[m][n][hr*2]   + b1s[c],   0.f);
                float h1 = fmaxf(acc[m][n][hr*2+1] + b1s[c+1], 0.f);
                p = fmaf(h0, w2s[c], p);
                p = fmaf(h1, w2s[c+1], p);
            }
            p += __shfl_xor_sync(~0u, p, 1);
            p += __shfl_xor_sync(~0u, p, 2);
            if ((lane & 3) == 0) red[wm*64 + m*16 + (lane>>2) + hr*8][wn] = p;
        }
    }
    __syncthreads();
    if (tid < 128) {
        float lg = b2v[0] + red[tid][0] + red[tid][1] + red[tid][2] + red[tid][3];
        float s;
        if (lg >= 0.f) { s = 1.f / (1.f + expf(-lg)); }
        else           { float e = expf(lg); s = e / (1.f + e); }
        int t = tM + tid;
        int idx = (t & (BB-1)) * NN + (t >> 4);
        g_sig[idx] = s;
        if (g_valid[idx] && fabsf(s - 0.5f) <= BAND) {
            int p = atomicAdd(&g_cnt0, 1);
            if (p < RCCAP) g_list0[p] = idx;
        }
    }
}

// -------------------- exact fp32 recompute of flagged tokens --------------------
__global__ void __launch_bounds__(128) recheck_kernel(
    const float* __restrict__ x, const float* __restrict__ w1,
    const float* __restrict__ b1v, const float* __restrict__ w2v,
    const float* __restrict__ b2v, int which)
{
    __shared__ float wred[4];
    int cnt = min(which ? g_cnt1 : g_cnt0, RCCAP);
    const int* list = which ? g_list1 : g_list0;
    int j = threadIdx.x;
    for (int it = blockIdx.x; it < cnt; it += gridDim.x) {
        int tok = list[it];
        int b = tok >> 12, n = tok & (NN - 1);
        const float* xr = &x[(n * BB + b) * CC];
        float a = 0.f;
        #pragma unroll 8
        for (int k = 0; k < CC; k++) a = fmaf(xr[k], w1[k * HH + j], a);
        float h = fmaxf(a + b1v[j], 0.f);
        float p = h * w2v[j];
        #pragma unroll
        for (int o = 16; o; o >>= 1) p += __shfl_down_sync(~0u, p, o);
        if ((j & 31) == 0) wred[j >> 5] = p;
        __syncthreads();
        if (j == 0) {
            float lg = b2v[0] + wred[0] + wred[1] + wred[2] + wred[3];
            float s;
            if (lg >= 0.f) { s = 1.f / (1.f + expf(-lg)); }
            else           { float e = expf(lg); s = e / (1.f + e); }
            g_sig[tok] = s;
        }
        __syncthreads();
    }
}

// -------------------- block scan (inclusive) via warp shuffles --------------------
__device__ __forceinline__ int block_scan_incl(int v, int tid, int* warpsum) {
    __syncthreads();
    int lane = tid & 31, w = tid >> 5;
    int s = v;
    #pragma unroll
    for (int o = 1; o < 32; o <<= 1) {
        int t = __shfl_up_sync(~0u, s, o);
        if (lane >= o) s += t;
    }
    if (lane == 31) warpsum[w] = s;
    __syncthreads();
    if (w == 0) {
        int ws = (lane < 16) ? warpsum[lane] : 0;
        #pragma unroll
        for (int o = 1; o < 16; o <<= 1) {
            int t = __shfl_up_sync(~0u, ws, o);
            if (lane >= o) ws += t;
        }
        if (lane < 16) warpsum[lane] = ws;
    }
    __syncthreads();
    return s + ((w > 0) ? warpsum[w - 1] : 0);
}

// -------------------- selection: 3-pass radix select; phase 0 = threshold + band flags ----
__global__ void __launch_bounds__(512) select_kernel(int phase) {
    const int T = 512;
    int set = blockIdx.x;
    int b = blockIdx.y;
    int tid = threadIdx.x;

    __shared__ int hist[4096];
    __shared__ int sh[T];
    __shared__ int s_warp[16];
    __shared__ int s_scal[8];

    const float* sig = g_sig + b * NN;
    const unsigned char* vd = g_valid + b * NN;

    if (tid < 8) s_scal[tid] = 0;
    __syncthreads();
    int cs = 0, cd = 0;
    for (int n = tid; n < NN; n += T) {
        if (vd[n]) { if (sig[n] >= 0.5f) cs++; else cd++; }
    }
    #pragma unroll
    for (int o = 16; o; o >>= 1) {
        cs += __shfl_down_sync(~0u, cs, o);
        cd += __shfl_down_sync(~0u, cd, o);
    }
    if ((tid & 31) == 0) { atomicAdd(&s_scal[0], cs); atomicAdd(&s_scal[1], cd); }
    __syncthreads();
    int mc = min(s_scal[0], s_scal[1]);
    if (phase == 1 && set == 0 && tid == 0) g_mc[b] = mc;
    if (mc == 0) {
        if (phase == 0 && tid == 0) g_thr[set][b] = 0x7FC00000u;
        return;
    }

    int k = mc;
    unsigned thrV = 0, hm = 0;
    const int widths[3] = {12, 10, 10};
    const int shifts[3] = {20, 10, 0};

    for (int p = 0; p < 3; p++) {
        int shift = shifts[p];
        int nb2 = 1 << widths[p];
        int CHn = nb2 >> 9;
        for (int i = tid; i < nb2; i += T) hist[i] = 0;
        __syncthreads();
        for (int n = tid; n < NN; n += T) {
            if (!vd[n]) continue;
            float s = sig[n];
            bool in = set ? (s < 0.5f) : (s >= 0.5f);
            if (!in) continue;
            unsigned bits = __float_as_uint(s);
            if ((bits & hm) != thrV) continue;
            atomicAdd(&hist[(bits >> shift) & (nb2 - 1)], 1);
        }
        __syncthreads();
        int base = tid * CHn, csum = 0;
        for (int i = 0; i < CHn; i++) csum += hist[base + i];
        int P = block_scan_incl(csum, tid, s_warp);
        sh[tid] = P;
        if (tid == T - 1) s_scal[5] = P;
        __syncthreads();
        int Tt = s_scal[5];
        if (P - csum <= Tt - k && P > Tt - k) s_scal[2] = tid;
        __syncthreads();
        if (tid == 0) {
            int cc = s_scal[2];
            int above = Tt - sh[cc];
            int dg = cc * CHn;
            for (int d = cc * CHn + CHn - 1; d >= cc * CHn; d--) {
                int c = hist[d];
                if (above + c >= k) { dg = d; break; }
                above += c;
            }
            s_scal[3] = dg;
            s_scal[4] = k - above;
        }
        __syncthreads();
        thrV |= ((unsigned)s_scal[3]) << shift;
        k = s_scal[4];
        hm |= ((unsigned)(nb2 - 1)) << shift;
        __syncthreads();
    }

    if (phase == 0) {
        if (tid == 0) g_thr[set][b] = thrV;
        // fused flagthr: this block owns (set, b); flag in-set tokens near threshold
        float tf = __uint_as_float(thrV);
        for (int n = tid; n < NN; n += T) {
            if (!vd[n]) continue;
            float s = sig[n];
            bool in = set ? (s < 0.5f) : (s >= 0.5f);
            if (in && fabsf(s - tf) <= BAND) {
                int p = atomicAdd(&g_cnt1, 1);
                if (p < RCCAP) g_list1[p] = b * NN + n;
            }
        }
        return;
    }
    int k_rem = k;

    int n0 = tid * 8;
    unsigned char gtf[8], eqf[8];
    int lgt = 0, leq = 0;
    #pragma unroll
    for (int q = 0; q < 8; q++) {
        int n = n0 + q;
        float s = sig[n];
        bool in = vd[n] && (set ? (s < 0.5f) : (s >= 0.5f));
        unsigned bits = __float_as_uint(s);
        gtf[q] = (in && bits > thrV) ? 1 : 0;
        eqf[q] = (in && bits == thrV) ? 1 : 0;
        lgt += gtf[q]; leq += eqf[q];
    }
    int own = lgt | (leq << 16);
    int pref = block_scan_incl(own, tid, s_warp) - own;
    int pgt = pref & 0xFFFF, peq = pref >> 16;
    int* dst = set ? g_discard_idx : g_split_idx;
    unsigned char* flag = g_selflag + b * NN;
    int cgi = 0, cei = 0;
    #pragma unroll
    for (int q = 0; q < 8; q++) {
        int n = n0 + q;
        if (gtf[q]) {
            int pos = (pgt + cgi) + min(peq + cei, k_rem);
            dst[b * MAXSEL + pos] = n;
            flag[n] = 1;
            cgi++;
        } else if (eqf[q]) {
            int er = peq + cei;
            if (er < k_rem) {
                int pos = (pgt + cgi) + er;
                dst[b * MAXSEL + pos] = n;
                flag[n] = 1;
            }
            cei++;
        }
    }
}

// -------------------- flag-gated copy --------------------
__global__ void __launch_bounds__(256) copyx_kernel(
    const float4* __restrict__ x4, float4* __restrict__ out4)
{
    int idx = blockIdx.x * 256 + threadIdx.x;
    int t = idx >> 6;
    int b = t & (BB - 1), n = t >> 4;
    if (!g_selflag[b * NN + n]) out4[idx] = x4[idx];
}

// -------------------- pair GEMM (bf16x2 split, double-buffered smem, k-tile 16) --------
__global__ void __launch_bounds__(256) pair_mma_kernel(
    const float* __restrict__ x, const float* __restrict__ bsv, float* __restrict__ out)
{
    int b = blockIdx.z;
    int mc = g_mc[b];
    int i0 = blockIdx.y * 64;
    if (i0 >= mc) return;
    int nb0 = blockIdx.x * 128;
    int half = nb0 >> 8;

    __shared__ __nv_bfloat16 sAhi[2][64][24], sAlo[2][64][24];
    __shared__ __nv_bfloat16 sBhi[2][16][136], sBlo[2][16][136];
    __shared__ float bss[128];
    __shared__ int srcI[64], tgtI[64];

    int tid = threadIdx.x;
    int lane = tid & 31;
    int wid = tid >> 5;

    if (tid < 128) bss[tid] = bsv[nb0 + tid];
    if (tid < 64) {
        int i = i0 + tid;
        if (i < mc) {
            int m = g_split_idx[b * MAXSEL + i];
            srcI[tid] = m;
            tgtI[tid] = half ? g_discard_idx[b * MAXSEL + i] : m;
        } else { srcI[tid] = 0; tgtI[tid] = -1; }
    }
    __syncthreads();

    int m_off = (wid >> 2) * 32;
    int n_off = (wid & 3) * 32;

    float acc[2][4][4];
    #pragma unroll
    for (int m = 0; m < 2; m++)
        #pragma unroll
        for (int j = 0; j < 4; j++)
            #pragma unroll
            for (int q = 0; q < 4; q++) acc[m][j][q] = 0.f;

    int ar = tid >> 2, aseg = (tid & 3) * 4;
    const float* xrow = &x[(srcI[ar] * BB + b) * CC + aseg];
    int br = tid >> 4, bcol = (tid & 15) * 8;

    float4 f0;
    uint4 bhR, blR;

#define PFETCH(kt) { \
    f0 = *(const float4*)&xrow[kt]; \
    bhR = *(const uint4*)&g_ws_hi[((kt) + br) * C2 + nb0 + bcol]; \
    blR = *(const uint4*)&g_ws_lo[((kt) + br) * C2 + nb0 + bcol]; }

#define PSTORE(db) { \
    float fv[4] = {f0.x, f0.y, f0.z, f0.w}; \
    __nv_bfloat162 hp[2], lp[2]; \
    _Pragma("unroll") \
    for (int q = 0; q < 2; q++) { \
        __nv_bfloat16 h0 = __float2bfloat16(fv[2*q]); \
        __nv_bfloat16 h1 = __float2bfloat16(fv[2*q+1]); \
        __nv_bfloat16 l0 = __float2bfloat16(fv[2*q]   - __bfloat162float(h0)); \
        __nv_bfloat16 l1 = __float2bfloat16(fv[2*q+1] - __bfloat162float(h1)); \
        hp[q] = __nv_bfloat162(h0, h1); \
        lp[q] = __nv_bfloat162(l0, l1); \
    } \
    *(uint2*)&sAhi[db][ar][aseg] = *(uint2*)hp; \
    *(uint2*)&sAlo[db][ar][aseg] = *(uint2*)lp; \
    *(uint4*)&sBhi[db][br][bcol] = bhR; \
    *(uint4*)&sBlo[db][br][bcol] = blR; }

#define PCOMPUTE(db) { \
    uint32_t ahi[2][4], alo[2][4], bhi[4][2], blo[4][2]; \
    _Pragma("unroll") \
    for (int m = 0; m < 2; m++) { \
        int arow = m_off + m * 16 + (lane & 15); \
        int acol = (lane >> 4) * 8; \
        ldsm_x4(ahi[m][0], ahi[m][1], ahi[m][2], ahi[m][3], smem_u32(&sAhi[db][arow][acol])); \
        ldsm_x4(alo[m][0], alo[m][1], alo[m][2], alo[m][3], smem_u32(&sAlo[db][arow][acol])); \
    } \
    _Pragma("unroll") \
    for (int g = 0; g < 2; g++) { \
        int brow = lane & 15; \
        int bcl = n_off + g * 16 + (lane >> 4) * 8; \
        uint32_t r0, r1, r2, r3; \
        ldsm_x4t(r0, r1, r2, r3, smem_u32(&sBhi[db][brow][bcl])); \
        bhi[2*g][0] = r0; bhi[2*g][1] = r1; bhi[2*g+1][0] = r2; bhi[2*g+1][1] = r3; \
        ldsm_x4t(r0, r1, r2, r3, smem_u32(&sBlo[db][brow][bcl])); \
        blo[2*g][0] = r0; blo[2*g][1] = r1; blo[2*g+1][0] = r2; blo[2*g+1][1] = r3; \
    } \
    _Pragma("unroll") \
    for (int m = 0; m < 2; m++) \
        _Pragma("unroll") \
        for (int j = 0; j < 4; j++) { \
            mma_bf16(acc[m][j], ahi[m], bhi[j]); \
            mma_bf16(acc[m][j], ahi[m], blo[j]); \
            mma_bf16(acc[m][j], alo[m], bhi[j]); \
        } }

    PFETCH(0); PSTORE(0); __syncthreads();
    int db = 0;
    for (int kt = 16; kt < CC; kt += 16) {
        PFETCH(kt);
        PCOMPUTE(db);
        PSTORE(db ^ 1);
        __syncthreads();
        db ^= 1;
    }
    PCOMPUTE(db);

#undef PFETCH
#undef PSTORE
#undef PCOMPUTE

    #pragma unroll
    for (int m = 0; m < 2; m++) {
        #pragma unroll
        for (int hr = 0; hr < 2; hr++) {
            int r = m_off + m * 16 + (lane >> 2) + hr * 8;
            int tg = tgtI[r];
            if (tg < 0) continue;
            float* orow = &out[(tg * BB + b) * CC];
            #pragma unroll
            for (int j = 0; j < 4; j++) {
                int cl = n_off + j * 8 + (lane & 3) * 2;
                int cg = (nb0 + cl) & (CC - 1);
                float v0 = fmaxf(acc[m][j][hr*2]     + bss[cl],     0.f);
                float v1 = fmaxf(acc[m][j][hr*2 + 1] + bss[cl + 1], 0.f);
                float2 v = make_float2(v0, v1);
                *(float2*)&orow[cg] = v;
            }
        }
    }
}

// -------------------- launch --------------------
extern "C" void kernel_launch(void* const* d_in, const int* in_sizes, int n_in,
                              void* d_out, int out_size) {
    const float* x   = (const float*)d_in[0];
    const void*  msk = d_in[1];
    const float* w1  = (const float*)d_in[2];
    const float* b1  = (const float*)d_in[3];
    const float* w2  = (const float*)d_in[4];
    const float* b2  = (const float*)d_in[5];
    const float* ws  = (const float*)d_in[6];
    const float* bs  = (const float*)d_in[7];
    float* out = (float*)d_out;

    detect_mask_kernel<<<1, 1024>>>((const unsigned char*)msk);
    expand_mask_kernel<<<NTOK / 256, 256>>>(msk);
    prep_weights_kernel<<<(CC * C2) / 256, 256>>>(ws, w1);

    gating_mma_kernel<<<NTOK / 128, 256>>>(x, b1, w2, b2);
    recheck_kernel<<<512, 128>>>(x, w1, b1, w2, b2, 0);
    select_kernel<<<dim3(2, BB), 512>>>(0);
    recheck_kernel<<<512, 128>>>(x, w1, b1, w2, b2, 1);
    select_kernel<<<dim3(2, BB), 512>>>(1);
    copyx_kernel<<<(NTOK * (CC/4)) / 256, 256>>>((const float4*)x, (float4*)out);
    pair_mma_kernel<<<dim3(4, MAXSEL / 64, BB), 256>>>(x, bs, out);
}